// round 2
// baseline (speedup 1.0000x reference)
#include <cuda_runtime.h>

// ---------------------------------------------------------------------------
// Retriever: out[e] = relu([q | h_e[h] | r_emb[r] | h_e[t]] @ W1 + b1) @ W2 + b2
// Restructured:
//   c      = q @ W1[0:128] + b1                      (128)
//   R      = rel_embs @ W1[270:398]                  (500 x 128)
//   AB     = h_e @ [W1[128:270] | W1[398:540]]       (N x 256)  -- ONE GEMM
//   out[e] = W2 . relu(AB[h,0:128] + AB[t,128:256] + R[r] + c) + b2
// h_e = [emb(128) | topic(2) | 3 fwd DDE rounds (2 each) | 3 rev rounds (2 each)]
// ---------------------------------------------------------------------------

#define E_MAX 500000
#define N_MAX 100000
#define HE_W  144      // padded h_e row width (142 used, 2 zero pad)
#define AB_W  256

__device__ int    g_is64;
__device__ int    g_hh[E_MAX];
__device__ int    g_tt[E_MAX];
__device__ int    g_rr[E_MAX];
__device__ float  g_cnt_t[N_MAX];
__device__ float  g_cnt_h[N_MAX];
__device__ float  g_acc[2 * N_MAX];
__device__ float4 g_he4[(size_t)N_MAX * (HE_W / 4)];   // h_e [N,144]
__device__ float4 g_ab4[(size_t)N_MAX * (AB_W / 4)];   // AB  [N,256]
__device__ float4 g_w4[144 * 64];                      // Wcat [144,256]
__device__ float4 g_rm4[512 * 32];                     // R [NREL,128]
__device__ float4 g_c4[32];                            // c [128]

// ---------------- dtype detection: int64 vs int32 ids ----------------
// If ids are really int32, reading pairs as int64 yields (hi*2^32 + lo); for the
// r-id buffer hi is a relation id that is 0 with prob ~1/NREL, so the value is
// >= 2^32 almost surely. Require BOTH h-ids and r-ids to look like small int64s.
__global__ void k_detect(const void* ph, const void* pr, int E) {
    const long long* p = (const long long*)ph;
    const long long* q = (const long long*)pr;
    int ok = 1;
    for (int i = 0; i < 8; i++) {
        long long v = p[i];
        if (v < 0 || v >= 1000000) ok = 0;
        long long w = q[i];
        if (w < 0 || w >= 1000000) ok = 0;
    }
    g_is64 = ok;
}

// ---------------- zero counters / accumulator ----------------
__global__ void k_init(int Nn) {
    int i = blockIdx.x * 256 + threadIdx.x;
    if (i >= Nn) return;
    g_cnt_t[i] = 0.f;
    g_cnt_h[i] = 0.f;
    g_acc[2 * i] = 0.f;
    g_acc[2 * i + 1] = 0.f;
}

// ---------------- convert ids to int32 + degree counts ----------------
__global__ void k_convert(const void* ph, const void* pr, const void* pt, int E) {
    int e = blockIdx.x * 256 + threadIdx.x;
    if (e >= E) return;
    int h, r, t;
    if (g_is64) {
        h = (int)((const long long*)ph)[e];
        r = (int)((const long long*)pr)[e];
        t = (int)((const long long*)pt)[e];
    } else {
        h = ((const int*)ph)[e];
        r = ((const int*)pr)[e];
        t = ((const int*)pt)[e];
    }
    g_hh[e] = h; g_rr[e] = r; g_tt[e] = t;
    atomicAdd(&g_cnt_t[t], 1.0f);
    atomicAdd(&g_cnt_h[h], 1.0f);
}

// ---------------- build h_e cols 0..129 (+ zero pad) ----------------
__global__ void k_fill(const float* __restrict__ ent, const float* __restrict__ nont,
                       const float* __restrict__ topic, int Nn, int Ntext) {
    int i = blockIdx.x * 256 + threadIdx.x;
    if (i >= Nn * 36) return;
    int node = i / 36, c4 = i % 36;
    float4 v;
    if (c4 < 32) {
        const float* src = (node < Ntext) ? (ent + (size_t)node * 128 + c4 * 4)
                                          : (nont + c4 * 4);
        v = *(const float4*)src;
    } else if (c4 == 32) {
        v.x = topic[2 * node]; v.y = topic[2 * node + 1]; v.z = 0.f; v.w = 0.f;
    } else {
        v.x = v.y = v.z = v.w = 0.f;
    }
    g_he4[(size_t)node * 36 + c4] = v;
}

// ---------------- DDE scatter: acc[dst] += cur[src] ----------------
// dir=0: src=h, dst=t ; dir=1: src=t, dst=h. colsel<0 -> cur=topic (stride 2),
// else cur = h_e column colsel (stride HE_W).
__global__ void k_scatter(int dir, const float* __restrict__ topic, int colsel, int E) {
    int e = blockIdx.x * 256 + threadIdx.x;
    if (e >= E) return;
    int s = dir ? g_tt[e] : g_hh[e];
    int d = dir ? g_hh[e] : g_tt[e];
    float x0, x1;
    if (colsel < 0) {
        x0 = __ldg(topic + 2 * (size_t)s);
        x1 = __ldg(topic + 2 * (size_t)s + 1);
    } else {
        const float* he = (const float*)g_he4;
        x0 = __ldg(he + (size_t)s * HE_W + colsel);
        x1 = __ldg(he + (size_t)s * HE_W + colsel + 1);
    }
    atomicAdd(&g_acc[2 * d], x0);
    atomicAdd(&g_acc[2 * d + 1], x1);
}

// ---------------- DDE finalize: mean, store into h_e, re-zero acc ----------------
__global__ void k_finalize(int dir, int outcol, int Nn) {
    int i = blockIdx.x * 256 + threadIdx.x;
    if (i >= Nn) return;
    float c = fmaxf(dir ? g_cnt_h[i] : g_cnt_t[i], 1.0f);
    float* he = (float*)g_he4;
    he[(size_t)i * HE_W + outcol]     = g_acc[2 * i] / c;
    he[(size_t)i * HE_W + outcol + 1] = g_acc[2 * i + 1] / c;
    g_acc[2 * i] = 0.f;
    g_acc[2 * i + 1] = 0.f;
}

// ---------------- pack Wcat[144,256] = [W1_h | W1_t] (zero-padded rows) ----------------
__global__ void k_wprep(const float* __restrict__ W1) {
    int i = blockIdx.x * 256 + threadIdx.x;
    if (i >= 144 * 256) return;
    int k = i >> 8, j = i & 255;
    float v = 0.f;
    if (k < 142) v = (j < 128) ? W1[(128 + k) * 128 + j] : W1[(398 + k) * 128 + (j - 128)];
    ((float*)g_w4)[i] = v;
}

// ---------------- R = rel_embs @ W1[270:398] ----------------
__global__ void k_rel(const float* __restrict__ rel, const float* __restrict__ W1, int NREL) {
    int r = blockIdx.x;
    int j = threadIdx.x;
    if (r >= NREL) return;
    __shared__ float rs[128];
    rs[j] = rel[(size_t)r * 128 + j];
    __syncthreads();
    float acc = 0.f;
#pragma unroll 8
    for (int k = 0; k < 128; k++) acc += rs[k] * __ldg(&W1[(270 + k) * 128 + j]);
    ((float*)g_rm4)[(size_t)r * 128 + j] = acc;
}

// ---------------- c = q @ W1[0:128] + b1 ----------------
__global__ void k_cvec(const float* __restrict__ q, const float* __restrict__ W1,
                       const float* __restrict__ b1) {
    int j = threadIdx.x;
    __shared__ float qs[128];
    qs[j] = q[j];
    __syncthreads();
    float acc = b1[j];
#pragma unroll 8
    for (int k = 0; k < 128; k++) acc += qs[k] * __ldg(&W1[k * 128 + j]);
    ((float*)g_c4)[j] = acc;
}

// ---------------- main GEMM: AB[N,256] = h_e[N,144] @ Wcat[144,256] ----------------
// 128x128 block tile, BK=16, 256 threads, 8x8 per-thread microtile.
#define BM 128
#define BN 128
#define BK 16
__global__ __launch_bounds__(256) void k_gemm(int Nn) {
    __shared__ __align__(16) float As[BK][BM + 4];   // k-major (transposed)
    __shared__ __align__(16) float Bs[BK][BN + 4];
    int m0 = blockIdx.x * BM;
    int n0 = blockIdx.y * BN;
    int tid = threadIdx.x;
    int ty = tid >> 4, tx = tid & 15;
    const float* he = (const float*)g_he4;
    const float* Wc = (const float*)g_w4;
    float acc[8][8];
#pragma unroll
    for (int i = 0; i < 8; i++)
#pragma unroll
        for (int j = 0; j < 8; j++) acc[i][j] = 0.f;

    for (int k0 = 0; k0 < 144; k0 += BK) {
        // load A tile (transpose into As[k][m])
#pragma unroll
        for (int it = 0; it < 2; it++) {
            int l = tid + 256 * it;
            int row = l >> 2, kq = l & 3;
            float4 v = make_float4(0.f, 0.f, 0.f, 0.f);
            int gr = m0 + row;
            if (gr < Nn) v = *(const float4*)(he + (size_t)gr * HE_W + k0 + kq * 4);
            As[kq * 4 + 0][row] = v.x;
            As[kq * 4 + 1][row] = v.y;
            As[kq * 4 + 2][row] = v.z;
            As[kq * 4 + 3][row] = v.w;
        }
        // load B tile
#pragma unroll
        for (int it = 0; it < 2; it++) {
            int l = tid + 256 * it;
            int row = l >> 5, cq = l & 31;
            float4 v = *(const float4*)(Wc + (size_t)(k0 + row) * 256 + n0 + cq * 4);
            *(float4*)&Bs[row][cq * 4] = v;
        }
        __syncthreads();
#pragma unroll
        for (int k = 0; k < BK; k++) {
            float a[8], b[8];
            *(float4*)(a)     = *(const float4*)&As[k][ty * 8];
            *(float4*)(a + 4) = *(const float4*)&As[k][ty * 8 + 4];
            *(float4*)(b)     = *(const float4*)&Bs[k][tx * 8];
            *(float4*)(b + 4) = *(const float4*)&Bs[k][tx * 8 + 4];
#pragma unroll
            for (int i = 0; i < 8; i++)
#pragma unroll
                for (int j = 0; j < 8; j++) acc[i][j] += a[i] * b[j];
        }
        __syncthreads();
    }
    float* AB = (float*)g_ab4;
#pragma unroll
    for (int i = 0; i < 8; i++) {
        int gm = m0 + ty * 8 + i;
        if (gm < Nn) {
            float* p = AB + (size_t)gm * AB_W + n0 + tx * 8;
            *(float4*)p       = make_float4(acc[i][0], acc[i][1], acc[i][2], acc[i][3]);
            *(float4*)(p + 4) = make_float4(acc[i][4], acc[i][5], acc[i][6], acc[i][7]);
        }
    }
}

// ---------------- edge stage: one warp per edge ----------------
__global__ __launch_bounds__(256) void k_edge(float* __restrict__ out,
                                              const float4* __restrict__ w2,
                                              const float* __restrict__ b2, int E) {
    int gt = blockIdx.x * 256 + threadIdx.x;
    int e = gt >> 5, lane = gt & 31;
    if (e >= E) return;
    int h = g_hh[e], t = g_tt[e], r = g_rr[e];
    float4 a  = g_ab4[(size_t)h * 64 + lane];        // A part: cols 0..127
    float4 b  = g_ab4[(size_t)t * 64 + 32 + lane];   // B part: cols 128..255
    float4 rv = g_rm4[(size_t)r * 32 + lane];
    float4 cv = g_c4[lane];
    float4 w  = __ldg(&w2[lane]);
    float s = fmaxf(a.x + b.x + rv.x + cv.x, 0.f) * w.x
            + fmaxf(a.y + b.y + rv.y + cv.y, 0.f) * w.y
            + fmaxf(a.z + b.z + rv.z + cv.z, 0.f) * w.z
            + fmaxf(a.w + b.w + rv.w + cv.w, 0.f) * w.w;
    s += __shfl_xor_sync(0xffffffff, s, 16);
    s += __shfl_xor_sync(0xffffffff, s, 8);
    s += __shfl_xor_sync(0xffffffff, s, 4);
    s += __shfl_xor_sync(0xffffffff, s, 2);
    s += __shfl_xor_sync(0xffffffff, s, 1);
    if (lane == 0) out[e] = s + __ldg(b2);
}

// ---------------------------------------------------------------------------
extern "C" void kernel_launch(void* const* d_in, const int* in_sizes, int n_in,
                              void* d_out, int out_size) {
    // input order: h_id, r_id, t_id, q_emb, entity_embs, [num_non_text scalar],
    //              relation_embs, topic_one_hot, non_text_emb, W1, b1, W2, b2
    int off = (n_in >= 13) ? 0 : -1;   // robust to scalar input being dropped
    const void*  ph    = d_in[0];
    const void*  pr    = d_in[1];
    const void*  pt    = d_in[2];
    const float* q     = (const float*)d_in[3];
    const float* ent   = (const float*)d_in[4];
    const float* rel   = (const float*)d_in[6 + off];
    const float* topic = (const float*)d_in[7 + off];
    const float* nont  = (const float*)d_in[8 + off];
    const float* W1    = (const float*)d_in[9 + off];
    const float* b1    = (const float*)d_in[10 + off];
    const float* W2    = (const float*)d_in[11 + off];
    const float* b2    = (const float*)d_in[12 + off];

    int E     = in_sizes[0];
    int Ntext = in_sizes[4] / 128;
    int NREL  = in_sizes[6 + off] / 128;
    int Nn    = in_sizes[7 + off] / 2;
    if (E > E_MAX) E = E_MAX;
    if (Nn > N_MAX) Nn = N_MAX;

    int gE = (E + 255) / 256;
    int gN = (Nn + 255) / 256;

    k_detect<<<1, 1>>>(ph, pr, E);
    k_init<<<gN, 256>>>(Nn);
    k_fill<<<(Nn * 36 + 255) / 256, 256>>>(ent, nont, topic, Nn, Ntext);
    k_convert<<<gE, 256>>>(ph, pr, pt, E);

    // forward DDE rounds: src=h, dst=t -> h_e cols 130,132,134
    for (int rd = 0; rd < 3; rd++) {
        int colsel = (rd == 0) ? -1 : 130 + 2 * (rd - 1);
        k_scatter<<<gE, 256>>>(0, topic, colsel, E);
        k_finalize<<<gN, 256>>>(0, 130 + 2 * rd, Nn);
    }
    // reverse DDE rounds: src=t, dst=h -> h_e cols 136,138,140
    for (int rd = 0; rd < 3; rd++) {
        int colsel = (rd == 0) ? -1 : 136 + 2 * (rd - 1);
        k_scatter<<<gE, 256>>>(1, topic, colsel, E);
        k_finalize<<<gN, 256>>>(1, 136 + 2 * rd, Nn);
    }

    k_wprep<<<144, 256>>>(W1);
    k_rel<<<NREL, 128>>>(rel, W1, NREL);
    k_cvec<<<1, 128>>>(q, W1, b1);

    dim3 ggrid((Nn + BM - 1) / BM, AB_W / BN);
    k_gemm<<<ggrid, 256>>>(Nn);

    k_edge<<<(E * 32 + 255) / 256, 256>>>((float*)d_out, (const float4*)W2, b2, E);
}

// round 3
// speedup vs baseline: 1.1459x; 1.1459x over previous
#include <cuda_runtime.h>
#include <cuda_bf16.h>
#include <cuda_fp16.h>

// ---------------------------------------------------------------------------
// Retriever: out[e] = relu([q | h_e[h] | r_emb[r] | h_e[t]] @ W1 + b1) @ W2 + b2
//   c      = q @ W1[0:128] + b1                      (128, fp32)
//   R      = rel_embs @ W1[270:398]                  (500 x 128, stored fp16)
//   AB     = h_e @ [W1[128:270] | W1[398:540]]       (N x 256, stored fp16)
//            -- tensor-core GEMM, split-bf16 (3 HMMA products, fp32 accum)
//   out[e] = W2 . relu(AB[h,0:128] + AB[t,128:256] + R[r] + c) + b2
// ---------------------------------------------------------------------------

#define E_MAX 500000
#define N_MAX 100000
#define HE_W  144      // padded h_e row width (142 used, 2 zero pad)
#define KPAD  24       // smem row pitch in bf16 (48B -> conflict-free ldmatrix)

__device__ int    g_hh[E_MAX];
__device__ int    g_tt[E_MAX];
__device__ int    g_rr[E_MAX];
__device__ float  g_cnt_t[N_MAX];
__device__ float  g_cnt_h[N_MAX];
__device__ float  g_accf[2 * N_MAX];                   // fwd DDE accumulator
__device__ float  g_accr[2 * N_MAX];                   // rev DDE accumulator
__device__ float4 g_he4[(size_t)N_MAX * (HE_W / 4)];   // h_e [N,144] fp32
__device__ uint2  g_abh2[(size_t)N_MAX * 64];          // AB  [N,256] fp16
__device__ float4 g_w4[144 * 64];                      // Wcat [144,256] fp32
__device__ uint2  g_rh2[512 * 32];                     // R [NREL,128] fp16
__device__ float  g_cf[128];                           // c fp32

// ---------------- build h_e cols 0..129 + zero pad + zero counters ----------
__global__ void k_fill(const float* __restrict__ ent, const float* __restrict__ nont,
                       const float* __restrict__ topic, int Nn, int Ntext) {
    int i = blockIdx.x * 256 + threadIdx.x;
    if (i >= Nn * 36) return;
    int node = i / 36, c4 = i % 36;
    float4 v;
    if (c4 < 32) {
        const float* src = (node < Ntext) ? (ent + (size_t)node * 128 + c4 * 4)
                                          : (nont + c4 * 4);
        v = *(const float4*)src;
    } else if (c4 == 32) {
        v.x = topic[2 * node]; v.y = topic[2 * node + 1]; v.z = 0.f; v.w = 0.f;
    } else {
        v.x = v.y = v.z = v.w = 0.f;
        if (c4 == 33) {  // piggyback: zero counters/accumulators for this node
            g_cnt_t[node] = 0.f; g_cnt_h[node] = 0.f;
            g_accf[2 * node] = 0.f; g_accf[2 * node + 1] = 0.f;
            g_accr[2 * node] = 0.f; g_accr[2 * node + 1] = 0.f;
        }
    }
    g_he4[(size_t)node * 36 + c4] = v;
}

// ---------------- ids -> int32 (+dtype detect) + degree counts ---------------
__global__ void k_convert(const void* ph, const void* pr, const void* pt, int E) {
    __shared__ int s64;
    if (threadIdx.x == 0) {
        // int64 vs int32 detection: if really int32, an int64 view of the r-id
        // buffer is >= 2^32 almost surely (hi word is a relation id, rarely 0).
        const long long* p = (const long long*)ph;
        const long long* q = (const long long*)pr;
        int ok = 1;
        for (int i = 0; i < 8; i++) {
            long long v = p[i]; if (v < 0 || v >= 1000000) ok = 0;
            long long w = q[i]; if (w < 0 || w >= 1000000) ok = 0;
        }
        s64 = ok;
    }
    __syncthreads();
    int e = blockIdx.x * 256 + threadIdx.x;
    if (e >= E) return;
    int h, r, t;
    if (s64) {
        h = (int)((const long long*)ph)[e];
        r = (int)((const long long*)pr)[e];
        t = (int)((const long long*)pt)[e];
    } else {
        h = ((const int*)ph)[e];
        r = ((const int*)pr)[e];
        t = ((const int*)pt)[e];
    }
    g_hh[e] = h; g_rr[e] = r; g_tt[e] = t;
    atomicAdd(&g_cnt_t[t], 1.0f);
    atomicAdd(&g_cnt_h[h], 1.0f);
}

// ------------- fused DDE scatter (fwd h->t AND rev t->h in one pass) --------
// cf/cr: source column in h_e for fwd/rev chains, or -1 for topic.
__global__ void k_scatter2(const float* __restrict__ topic, int cf, int cr, int E) {
    int e = blockIdx.x * 256 + threadIdx.x;
    if (e >= E) return;
    int h = g_hh[e], t = g_tt[e];
    const float2* he2 = (const float2*)g_he4;
    const float2* tp2 = (const float2*)topic;
    float2 xf = (cf < 0) ? __ldg(tp2 + h) : __ldg(he2 + (size_t)h * (HE_W / 2) + cf / 2);
    float2 xr = (cr < 0) ? __ldg(tp2 + t) : __ldg(he2 + (size_t)t * (HE_W / 2) + cr / 2);
    atomicAdd(&g_accf[2 * t],     xf.x);
    atomicAdd(&g_accf[2 * t + 1], xf.y);
    atomicAdd(&g_accr[2 * h],     xr.x);
    atomicAdd(&g_accr[2 * h + 1], xr.y);
}

// ------------- fused DDE finalize (both directions) -------------------------
__global__ void k_finalize2(int of, int orr, int Nn) {
    int i = blockIdx.x * 256 + threadIdx.x;
    if (i >= Nn) return;
    float ct = fmaxf(g_cnt_t[i], 1.0f);
    float ch = fmaxf(g_cnt_h[i], 1.0f);
    float* he = (float*)g_he4;
    he[(size_t)i * HE_W + of]      = g_accf[2 * i] / ct;
    he[(size_t)i * HE_W + of + 1]  = g_accf[2 * i + 1] / ct;
    he[(size_t)i * HE_W + orr]     = g_accr[2 * i] / ch;
    he[(size_t)i * HE_W + orr + 1] = g_accr[2 * i + 1] / ch;
    g_accf[2 * i] = 0.f; g_accf[2 * i + 1] = 0.f;
    g_accr[2 * i] = 0.f; g_accr[2 * i + 1] = 0.f;
}

// ------------- fused prep: Wcat pack | R = rel@W1_r (fp16) | c = q@W1_q+b1 --
__global__ void k_prep(const float* __restrict__ W1, const float* __restrict__ rel,
                       const float* __restrict__ q, const float* __restrict__ b1,
                       int NREL, int nrelb) {
    int bid = blockIdx.x;
    int tid = threadIdx.x;
    if (bid < 144) {                       // Wcat row bid
        int k = bid, j = tid;
        float v = 0.f;
        if (k < 142) v = (j < 128) ? W1[(128 + k) * 128 + j]
                                   : W1[(398 + k) * 128 + (j - 128)];
        ((float*)g_w4)[k * 256 + j] = v;
    } else if (bid < 144 + nrelb) {        // two relations per block
        __shared__ float rs[256];
        int r = (bid - 144) * 2 + (tid >> 7);
        int j = tid & 127;
        int base = tid & ~127;
        rs[tid] = (r < NREL) ? rel[(size_t)r * 128 + j] : 0.f;
        __syncthreads();
        if (r < NREL) {
            float acc = 0.f;
#pragma unroll 8
            for (int k = 0; k < 128; k++) acc += rs[base + k] * __ldg(&W1[(270 + k) * 128 + j]);
            ((__half*)g_rh2)[(size_t)r * 128 + j] = __float2half(acc);
        }
    } else {                               // c vector
        __shared__ float qs[128];
        if (tid < 128) qs[tid] = q[tid];
        __syncthreads();
        if (tid < 128) {
            float acc = b1[tid];
#pragma unroll 8
            for (int k = 0; k < 128; k++) acc += qs[k] * __ldg(&W1[k * 128 + tid]);
            g_cf[tid] = acc;
        }
    }
}

// ---------------------------------------------------------------------------
// GEMM: AB[N,256] = h_e[N,144] @ Wcat[144,256], tensor cores, split-bf16.
// Block 128x128, 8 warps (2x4), warp tile 64x32, BK=16, output fp16.
// ---------------------------------------------------------------------------
__device__ __forceinline__ void ldsm4(unsigned* r, const void* p) {
    unsigned a = (unsigned)__cvta_generic_to_shared(p);
    asm volatile("ldmatrix.sync.aligned.m8n8.x4.shared.b16 {%0,%1,%2,%3}, [%4];"
                 : "=r"(r[0]), "=r"(r[1]), "=r"(r[2]), "=r"(r[3]) : "r"(a));
}
__device__ __forceinline__ void mma_bf16(float* d, const unsigned* a, unsigned b0, unsigned b1) {
    asm volatile("mma.sync.aligned.m16n8k16.row.col.f32.bf16.bf16.f32 "
                 "{%0,%1,%2,%3}, {%4,%5,%6,%7}, {%8,%9}, {%0,%1,%2,%3};"
                 : "+f"(d[0]), "+f"(d[1]), "+f"(d[2]), "+f"(d[3])
                 : "r"(a[0]), "r"(a[1]), "r"(a[2]), "r"(a[3]), "r"(b0), "r"(b1));
}
__device__ __forceinline__ unsigned pack2(__nv_bfloat16 x, __nv_bfloat16 y) {
    __nv_bfloat162 t = __halves2bfloat162(x, y);
    return *(unsigned*)&t;
}

__global__ __launch_bounds__(256) void k_gemm(int Nn) {
    __shared__ __align__(16) __nv_bfloat16 sAh[128 * KPAD];
    __shared__ __align__(16) __nv_bfloat16 sAl[128 * KPAD];
    __shared__ __align__(16) __nv_bfloat16 sBh[128 * KPAD];
    __shared__ __align__(16) __nv_bfloat16 sBl[128 * KPAD];
    int tid = threadIdx.x;
    int m0 = blockIdx.x * 128, n0 = blockIdx.y * 128;
    int wid = tid >> 5, lane = tid & 31;
    int wm = (wid >> 2) * 64, wn = (wid & 3) * 32;
    const float* he = (const float*)g_he4;
    const float* Wc = (const float*)g_w4;

    float acc[4][4][4];
#pragma unroll
    for (int i = 0; i < 4; i++)
#pragma unroll
        for (int j = 0; j < 4; j++)
#pragma unroll
            for (int k = 0; k < 4; k++) acc[i][j][k] = 0.f;

    int ldrow = lane & 15, ldk = (lane >> 4) * 8;

    for (int k0 = 0; k0 < HE_W; k0 += 16) {
        // ---- stage A tile (128x16 fp32 -> split bf16, row-major [m][k]) ----
#pragma unroll
        for (int it = 0; it < 2; it++) {
            int idx = tid + 256 * it;
            int row = idx >> 2, kq = idx & 3;
            float4 v = make_float4(0.f, 0.f, 0.f, 0.f);
            int gr = m0 + row;
            if (gr < Nn) v = *(const float4*)(he + (size_t)gr * HE_W + k0 + kq * 4);
            __nv_bfloat16 hx = __float2bfloat16(v.x), hy = __float2bfloat16(v.y);
            __nv_bfloat16 hz = __float2bfloat16(v.z), hw = __float2bfloat16(v.w);
            __nv_bfloat16 lx = __float2bfloat16(v.x - __bfloat162float(hx));
            __nv_bfloat16 ly = __float2bfloat16(v.y - __bfloat162float(hy));
            __nv_bfloat16 lz = __float2bfloat16(v.z - __bfloat162float(hz));
            __nv_bfloat16 lw = __float2bfloat16(v.w - __bfloat162float(hw));
            uint2* ph = (uint2*)(sAh + row * KPAD + kq * 4);
            uint2* pl = (uint2*)(sAl + row * KPAD + kq * 4);
            *ph = make_uint2(pack2(hx, hy), pack2(hz, hw));
            *pl = make_uint2(pack2(lx, ly), pack2(lz, lw));
        }
        // ---- stage B tile (16x128 fp32 -> split bf16, TRANSPOSED [n][k]) ----
#pragma unroll
        for (int it = 0; it < 2; it++) {
            int idx = tid + 256 * it;
            int row = idx >> 5, cq = idx & 31;     // row = k (0..15), cq*4 = n
            float4 v = *(const float4*)(Wc + (size_t)(k0 + row) * 256 + n0 + cq * 4);
            float f[4] = {v.x, v.y, v.z, v.w};
#pragma unroll
            for (int j = 0; j < 4; j++) {
                __nv_bfloat16 h = __float2bfloat16(f[j]);
                __nv_bfloat16 l = __float2bfloat16(f[j] - __bfloat162float(h));
                sBh[(cq * 4 + j) * KPAD + row] = h;
                sBl[(cq * 4 + j) * KPAD + row] = l;
            }
        }
        __syncthreads();

        // ---- fragments ----
        unsigned Ah[4][4], Al[4][4], Bh[2][4], Bl[2][4];
#pragma unroll
        for (int mf = 0; mf < 4; mf++) {
            ldsm4(Ah[mf], sAh + (wm + mf * 16 + ldrow) * KPAD + ldk);
            ldsm4(Al[mf], sAl + (wm + mf * 16 + ldrow) * KPAD + ldk);
        }
#pragma unroll
        for (int nh = 0; nh < 2; nh++) {
            ldsm4(Bh[nh], sBh + (wn + nh * 16 + ldrow) * KPAD + ldk);
            ldsm4(Bl[nh], sBl + (wn + nh * 16 + ldrow) * KPAD + ldk);
        }
        // ---- 3-product split-bf16 MMA ----
#pragma unroll
        for (int mf = 0; mf < 4; mf++)
#pragma unroll
            for (int nf = 0; nf < 4; nf++) {
                int nh = nf >> 1, sel = nf & 1;
                unsigned bh0 = Bh[nh][sel], bh1 = Bh[nh][sel + 2];
                unsigned bl0 = Bl[nh][sel], bl1 = Bl[nh][sel + 2];
                mma_bf16(acc[mf][nf], Ah[mf], bh0, bh1);   // hi*hi
                mma_bf16(acc[mf][nf], Ah[mf], bl0, bl1);   // hi*lo
                mma_bf16(acc[mf][nf], Al[mf], bh0, bh1);   // lo*hi
            }
        __syncthreads();
    }

    // ---- epilogue: fp32 acc -> fp16 AB ----
    int g = lane >> 2, tg = lane & 3;
    unsigned* outw = (unsigned*)g_abh2;
#pragma unroll
    for (int mf = 0; mf < 4; mf++)
#pragma unroll
        for (int nf = 0; nf < 4; nf++) {
            int col = n0 + wn + nf * 8 + 2 * tg;       // even column
            int r0 = m0 + wm + mf * 16 + g;
            if (r0 < Nn) {
                __half2 p = __floats2half2_rn(acc[mf][nf][0], acc[mf][nf][1]);
                outw[(size_t)r0 * 128 + (col >> 1)] = *(unsigned*)&p;
            }
            int r1 = r0 + 8;
            if (r1 < Nn) {
                __half2 p = __floats2half2_rn(acc[mf][nf][2], acc[mf][nf][3]);
                outw[(size_t)r1 * 128 + (col >> 1)] = *(unsigned*)&p;
            }
        }
}

// ---------------- edge stage: one warp per edge, fp16 gathers ----------------
__global__ __launch_bounds__(256) void k_edge(float* __restrict__ out,
                                              const float4* __restrict__ w2,
                                              const float* __restrict__ b2, int E) {
    int gt = blockIdx.x * 256 + threadIdx.x;
    int e = gt >> 5, lane = gt & 31;
    if (e >= E) return;
    int h = g_hh[e], t = g_tt[e], r = g_rr[e];
    uint2 ua = __ldg(&g_abh2[(size_t)h * 64 + lane]);        // cols 0..127
    uint2 ub = __ldg(&g_abh2[(size_t)t * 64 + 32 + lane]);   // cols 128..255
    uint2 ur = __ldg(&g_rh2[(size_t)r * 32 + lane]);
    float4 cv = __ldg(&((const float4*)g_cf)[lane]);
    float4 w  = __ldg(&w2[lane]);
    float2 a0 = __half22float2(*(__half2*)&ua.x), a1 = __half22float2(*(__half2*)&ua.y);
    float2 b0 = __half22float2(*(__half2*)&ub.x), b1 = __half22float2(*(__half2*)&ub.y);
    float2 r0 = __half22float2(*(__half2*)&ur.x), r1 = __half22float2(*(__half2*)&ur.y);
    float s = fmaxf(a0.x + b0.x + r0.x + cv.x, 0.f) * w.x
            + fmaxf(a0.y + b0.y + r0.y + cv.y, 0.f) * w.y
            + fmaxf(a1.x + b1.x + r1.x + cv.z, 0.f) * w.z
            + fmaxf(a1.y + b1.y + r1.y + cv.w, 0.f) * w.w;
    s += __shfl_xor_sync(0xffffffff, s, 16);
    s += __shfl_xor_sync(0xffffffff, s, 8);
    s += __shfl_xor_sync(0xffffffff, s, 4);
    s += __shfl_xor_sync(0xffffffff, s, 2);
    s += __shfl_xor_sync(0xffffffff, s, 1);
    if (lane == 0) out[e] = s + __ldg(b2);
}

// ---------------------------------------------------------------------------
extern "C" void kernel_launch(void* const* d_in, const int* in_sizes, int n_in,
                              void* d_out, int out_size) {
    int off = (n_in >= 13) ? 0 : -1;   // robust to scalar input being dropped
    const void*  ph    = d_in[0];
    const void*  pr    = d_in[1];
    const void*  pt    = d_in[2];
    const float* q     = (const float*)d_in[3];
    const float* ent   = (const float*)d_in[4];
    const float* rel   = (const float*)d_in[6 + off];
    const float* topic = (const float*)d_in[7 + off];
    const float* nont  = (const float*)d_in[8 + off];
    const float* W1    = (const float*)d_in[9 + off];
    const float* b1    = (const float*)d_in[10 + off];
    const float* W2    = (const float*)d_in[11 + off];
    const float* b2    = (const float*)d_in[12 + off];

    int E     = in_sizes[0];
    int Ntext = in_sizes[4] / 128;
    int NREL  = in_sizes[6 + off] / 128;
    int Nn    = in_sizes[7 + off] / 2;
    if (E > E_MAX) E = E_MAX;
    if (Nn > N_MAX) Nn = N_MAX;
    if (NREL > 512) NREL = 512;

    int gE = (E + 255) / 256;
    int gN = (Nn + 255) / 256;
    int nrelb = (NREL + 1) / 2;

    k_fill<<<(Nn * 36 + 255) / 256, 256>>>(ent, nont, topic, Nn, Ntext);
    k_convert<<<gE, 256>>>(ph, pr, pt, E);

    // 3 fused DDE rounds (fwd cols 130/132/134, rev cols 136/138/140)
    for (int rd = 0; rd < 3; rd++) {
        int cf = (rd == 0) ? -1 : 130 + 2 * (rd - 1);
        int cr = (rd == 0) ? -1 : 136 + 2 * (rd - 1);
        k_scatter2<<<gE, 256>>>(topic, cf, cr, E);
        k_finalize2<<<gN, 256>>>(130 + 2 * rd, 136 + 2 * rd, Nn);
    }

    k_prep<<<144 + nrelb + 1, 256>>>(W1, rel, q, b1, NREL, nrelb);

    dim3 ggrid((Nn + 127) / 128, 2);
    k_gemm<<<ggrid, 256>>>(Nn);

    k_edge<<<(E * 32 + 255) / 256, 256>>>((float*)d_out, (const float4*)W2, b2, E);
}

// round 4
// speedup vs baseline: 1.5363x; 1.3407x over previous
#include <cuda_runtime.h>
#include <cuda_bf16.h>
#include <cuda_fp16.h>

// ---------------------------------------------------------------------------
// Retriever: out[e] = relu([q | h_e[h] | r_emb[r] | h_e[t]] @ W1 + b1) @ W2 + b2
//   R'     = rel_embs @ W1[270:398] + (q @ W1[0:128] + b1)    (500 x 128, fp16)
//   AB     = h_e @ [W1[128:270] | W1[398:540]]                (N x 256, fp16)
//            split-bf16 tensor-core GEMM (3 HMMA products, fp32 accum),
//            inputs pre-split to bf16 hi/lo; DDE columns synthesized in-GEMM.
//   out[e] = W2 . relu(AB[h,0:128] + AB[t,128:256] + R'[r]) + b2
// ---------------------------------------------------------------------------

#define E_MAX 500000
#define N_MAX 100000
#define HE_W  144      // padded row width (142 used): pitch for he / Wcat (bf16)

__device__ int    g_hh[E_MAX];
__device__ int    g_tt[E_MAX];
__device__ int    g_rr[E_MAX];
__device__ float  g_cnt_t[N_MAX];
__device__ float  g_cnt_h[N_MAX];
__device__ float  g_af[3][2 * N_MAX];                  // fwd DDE sums, rounds 1..3
__device__ float  g_ar[3][2 * N_MAX];                  // rev DDE sums
__device__ __nv_bfloat16 g_heh[(size_t)N_MAX * HE_W];  // h_e hi (cols 0..127 filled)
__device__ __nv_bfloat16 g_hel[(size_t)N_MAX * HE_W];  // h_e lo
__device__ __nv_bfloat16 g_wh[256 * HE_W];             // Wcat hi, [n][k]
__device__ __nv_bfloat16 g_wl[256 * HE_W];             // Wcat lo
__device__ uint2  g_abh2[(size_t)N_MAX * 64];          // AB  [N,256] fp16
__device__ uint2  g_rh2[512 * 32];                     // R' [NREL,128] fp16

__device__ __forceinline__ unsigned pack2(__nv_bfloat16 x, __nv_bfloat16 y) {
    __nv_bfloat162 t = __halves2bfloat162(x, y);
    return *(unsigned*)&t;
}
__device__ __forceinline__ void split1(float v, __nv_bfloat16& h, __nv_bfloat16& l) {
    h = __float2bfloat16(v);
    l = __float2bfloat16(v - __bfloat162float(h));
}

// ---------------- build h_e hi/lo cols 0..127 + zero DDE state ----------------
__global__ void k_fill(const float* __restrict__ ent, const float* __restrict__ nont,
                       int Nn, int Ntext) {
    int i = blockIdx.x * 256 + threadIdx.x;
    if (i >= Nn * 32) return;
    int node = i >> 5, c4 = i & 31;
    const float* src = (node < Ntext) ? (ent + (size_t)node * 128 + c4 * 4)
                                      : (nont + c4 * 4);
    float4 v = *(const float4*)src;
    __nv_bfloat16 hx, hy, hz, hw, lx, ly, lz, lw;
    split1(v.x, hx, lx); split1(v.y, hy, ly);
    split1(v.z, hz, lz); split1(v.w, hw, lw);
    size_t off = (size_t)node * HE_W + c4 * 4;
    *(uint2*)(g_heh + off) = make_uint2(pack2(hx, hy), pack2(hz, hw));
    *(uint2*)(g_hel + off) = make_uint2(pack2(lx, ly), pack2(lz, lw));
    if (c4 == 0) {   // piggyback: zero DDE counters/accumulators
        g_cnt_t[node] = 0.f; g_cnt_h[node] = 0.f;
#pragma unroll
        for (int rdx = 0; rdx < 3; rdx++) {
            g_af[rdx][2 * node] = 0.f; g_af[rdx][2 * node + 1] = 0.f;
            g_ar[rdx][2 * node] = 0.f; g_ar[rdx][2 * node + 1] = 0.f;
        }
    }
}

// ------- ids -> int32 (+dtype detect) + degree counts + DDE round-0 scatter ----
__global__ void k_convert(const void* ph, const void* pr, const void* pt,
                          const float* __restrict__ topic, int E) {
    __shared__ int s64;
    if (threadIdx.x == 0) {
        // int64 vs int32: int64 view of int32 r-id buffer is >= 2^32 a.s.
        const long long* p = (const long long*)ph;
        const long long* qq = (const long long*)pr;
        int ok = 1;
        for (int i = 0; i < 8; i++) {
            long long v = p[i];  if (v < 0 || v >= 1000000) ok = 0;
            long long w = qq[i]; if (w < 0 || w >= 1000000) ok = 0;
        }
        s64 = ok;
    }
    __syncthreads();
    int e = blockIdx.x * 256 + threadIdx.x;
    if (e >= E) return;
    int h, r, t;
    if (s64) {
        h = (int)((const long long*)ph)[e];
        r = (int)((const long long*)pr)[e];
        t = (int)((const long long*)pt)[e];
    } else {
        h = ((const int*)ph)[e];
        r = ((const int*)pr)[e];
        t = ((const int*)pt)[e];
    }
    g_hh[e] = h; g_rr[e] = r; g_tt[e] = t;
    atomicAdd(&g_cnt_t[t], 1.0f);
    atomicAdd(&g_cnt_h[h], 1.0f);
    const float2* tp2 = (const float2*)topic;
    float2 th = __ldg(tp2 + h);
    float2 tt = __ldg(tp2 + t);
    atomicAdd(&g_af[0][2 * t],     th.x);   // fwd: h -> t
    atomicAdd(&g_af[0][2 * t + 1], th.y);
    atomicAdd(&g_ar[0][2 * h],     tt.x);   // rev: t -> h
    atomicAdd(&g_ar[0][2 * h + 1], tt.y);
}

// ------- DDE scatter round rd (1 or 2): reads round rd-1 sums, normalizes -----
__global__ void k_scat(int rd, int E) {
    int e = blockIdx.x * 256 + threadIdx.x;
    if (e >= E) return;
    int h = g_hh[e], t = g_tt[e];
    float ct = fmaxf(__ldg(&g_cnt_t[h]), 1.0f);
    float ch = fmaxf(__ldg(&g_cnt_h[t]), 1.0f);
    float xf0 = __ldg(&g_af[rd - 1][2 * h])     / ct;
    float xf1 = __ldg(&g_af[rd - 1][2 * h + 1]) / ct;
    float xr0 = __ldg(&g_ar[rd - 1][2 * t])     / ch;
    float xr1 = __ldg(&g_ar[rd - 1][2 * t + 1]) / ch;
    atomicAdd(&g_af[rd][2 * t],     xf0);
    atomicAdd(&g_af[rd][2 * t + 1], xf1);
    atomicAdd(&g_ar[rd][2 * h],     xr0);
    atomicAdd(&g_ar[rd][2 * h + 1], xr1);
}

// ------- prep: Wcat split-bf16 [n][k] | R' = rel@W1_r + (q@W1_q + b1), fp16 ----
__global__ void k_prep(const float* __restrict__ W1, const float* __restrict__ rel,
                       const float* __restrict__ q, const float* __restrict__ b1,
                       int NREL) {
    int bid = blockIdx.x;
    int tid = threadIdx.x;
    if (bid < 144) {                       // Wcat: 256 elements of the [n][k] array
        int idx = bid * 256 + tid;
        int n = idx / 144, k = idx % 144;
        float v = 0.f;
        if (k < 142) v = (n < 128) ? W1[(128 + k) * 128 + n]
                                   : W1[(398 + k) * 128 + (n - 128)];
        __nv_bfloat16 h, l;
        split1(v, h, l);
        g_wh[idx] = h;
        g_wl[idx] = l;
    } else {                               // two relations per block
        __shared__ float rs[256];
        __shared__ float qs[128];
        int r = (bid - 144) * 2 + (tid >> 7);
        int j = tid & 127;
        int base = tid & ~127;
        if (tid < 128) qs[tid] = q[tid];
        rs[tid] = (r < NREL) ? rel[(size_t)r * 128 + j] : 0.f;
        __syncthreads();
        if (r < NREL) {
            float accc = b1[j];
#pragma unroll 8
            for (int k = 0; k < 128; k++) accc += qs[k] * __ldg(&W1[k * 128 + j]);
            float accr = 0.f;
#pragma unroll 8
            for (int k = 0; k < 128; k++) accr += rs[base + k] * __ldg(&W1[(270 + k) * 128 + j]);
            ((__half*)g_rh2)[(size_t)r * 128 + j] = __float2half(accc + accr);
        }
    }
}

// ---------------------------------------------------------------------------
// GEMM: AB[N,256] = h_e[N,144] @ Wcat[144,256], split-bf16 (3 products).
// Block 128(m) x 128(n), 8 warps (2x4), warp tile 64x32, BK=16.
// cp.async double-buffered staging; last k-tile (cols 128..143) synthesized
// from topic + DDE accumulators (no fp32 h_e, no finalize kernel).
// ---------------------------------------------------------------------------
#define APITCH 24   // smem row pitch in bf16 (48B -> conflict-free ldmatrix)

__device__ __forceinline__ void ldsm4(unsigned* r, unsigned a) {
    asm volatile("ldmatrix.sync.aligned.m8n8.x4.shared.b16 {%0,%1,%2,%3}, [%4];"
                 : "=r"(r[0]), "=r"(r[1]), "=r"(r[2]), "=r"(r[3]) : "r"(a));
}
__device__ __forceinline__ void mma_bf16(float* d, const unsigned* a, unsigned b0, unsigned b1) {
    asm volatile("mma.sync.aligned.m16n8k16.row.col.f32.bf16.bf16.f32 "
                 "{%0,%1,%2,%3}, {%4,%5,%6,%7}, {%8,%9}, {%0,%1,%2,%3};"
                 : "+f"(d[0]), "+f"(d[1]), "+f"(d[2]), "+f"(d[3])
                 : "r"(a[0]), "r"(a[1]), "r"(a[2]), "r"(a[3]), "r"(b0), "r"(b1));
}
__device__ __forceinline__ void cp16(unsigned dst, const void* src) {
    asm volatile("cp.async.ca.shared.global [%0], [%1], 16;" :: "r"(dst), "l"(src));
}

__global__ __launch_bounds__(256) void k_gemm(const float* __restrict__ topic, int Nn) {
    // smem: [sel(A/B)][buf][arr(hi/lo)][128*APITCH] bf16 = 48 KB
    __shared__ __align__(16) __nv_bfloat16 sm[8 * 128 * APITCH];
    unsigned smb = (unsigned)__cvta_generic_to_shared(sm);
    int tid = threadIdx.x;
    int m0 = blockIdx.x * 128, n0 = blockIdx.y * 128;
    int wid = tid >> 5, lane = tid & 31;
    int wm = (wid >> 2) * 64, wn = (wid & 3) * 32;

    // staging map: 4 slots/thread. slots 0,1 -> A ; 2,3 -> B.
    // per slot: rem in [0,512): row = rem>>2, q = rem&3 (arr=q>>1, half=q&1)
    int srow[4], shalf[4], sarr[4], ssel[4];
    const __nv_bfloat16* gbase[4];
    unsigned dstoff[4];   // smem byte offset excluding buf
#pragma unroll
    for (int s = 0; s < 4; s++) {
        int idx = tid + 256 * s;
        int sel = idx >> 9;            // 0 = A, 1 = B
        int rem = idx & 511;
        int row = rem >> 2, qq = rem & 3;
        int arr = qq >> 1, half = qq & 1;
        srow[s] = row; shalf[s] = half; sarr[s] = arr; ssel[s] = sel;
        if (sel == 0) {
            int gr = m0 + row; if (gr >= Nn) gr = Nn - 1;
            gbase[s] = (arr ? g_hel : g_heh) + (size_t)gr * HE_W + half * 8;
        } else {
            gbase[s] = (arr ? g_wl : g_wh) + (size_t)(n0 + row) * HE_W + half * 8;
        }
        // region: ((sel*2 + buf)*2 + arr)*3072 elems; buf added at use time
        dstoff[s] = ((unsigned)(sel * 4 + arr) * 3072 + row * APITCH + half * 8) * 2;
    }
    const unsigned bufstride = 2u * 3072u * 2u;   // bytes between buf0/buf1 regions

    float acc[4][4][4];
#pragma unroll
    for (int i = 0; i < 4; i++)
#pragma unroll
        for (int j = 0; j < 4; j++)
#pragma unroll
            for (int k = 0; k < 4; k++) acc[i][j][k] = 0.f;

    int ldrow = lane & 15, ldk = (lane >> 4) * 8;
    int synr = m0 + ((tid * 2) >> 2 >= 0 ? 0 : 0);  // (unused placeholder)

    // ---- prologue: stage tile 0 into buf 0 ----
#pragma unroll
    for (int s = 0; s < 4; s++) cp16(smb + dstoff[s], gbase[s]);
    asm volatile("cp.async.commit_group;");

    for (int it = 0; it <= 8; ++it) {
        int buf = it & 1;
        asm volatile("cp.async.wait_group 0;");
        __syncthreads();

        if (it < 8) {
            int nb = buf ^ 1;
            unsigned bofs = nb * bufstride;
            if (it + 1 < 8) {
#pragma unroll
                for (int s = 0; s < 4; s++)
                    cp16(smb + bofs + dstoff[s], gbase[s] + (it + 1) * 16);
            } else {
                // tile 8: B via cp.async (Wcat cols 128..143 are real/zero-padded),
                // A synthesized from topic + DDE accumulators.
#pragma unroll
                for (int s = 2; s < 4; s++)
                    cp16(smb + bofs + dstoff[s], gbase[s] + 8 * 16);
#pragma unroll
                for (int s = 0; s < 2; s++) {
                    int row = srow[s], half = shalf[s], arr = sarr[s];
                    int i = m0 + row; if (i >= Nn) i = Nn - 1;
                    float v[8];
                    if (half == 0) {  // cols 128..135: topic, fwd rounds 1..3
                        float2 tp = __ldg(((const float2*)topic) + i);
                        float ict = 1.0f / fmaxf(g_cnt_t[i], 1.0f);
                        v[0] = tp.x; v[1] = tp.y;
                        v[2] = g_af[0][2 * i] * ict; v[3] = g_af[0][2 * i + 1] * ict;
                        v[4] = g_af[1][2 * i] * ict; v[5] = g_af[1][2 * i + 1] * ict;
                        v[6] = g_af[2][2 * i] * ict; v[7] = g_af[2][2 * i + 1] * ict;
                    } else {          // cols 136..143: rev rounds 1..3, pad
                        float ich = 1.0f / fmaxf(g_cnt_h[i], 1.0f);
                        v[0] = g_ar[0][2 * i] * ich; v[1] = g_ar[0][2 * i + 1] * ich;
                        v[2] = g_ar[1][2 * i] * ich; v[3] = g_ar[1][2 * i + 1] * ich;
                        v[4] = g_ar[2][2 * i] * ich; v[5] = g_ar[2][2 * i + 1] * ich;
                        v[6] = 0.f; v[7] = 0.f;
                    }
                    unsigned w[4];
#pragma unroll
                    for (int p = 0; p < 4; p++) {
                        __nv_bfloat16 h0, l0, h1, l1;
                        split1(v[2 * p], h0, l0);
                        split1(v[2 * p + 1], h1, l1);
                        w[p] = arr ? pack2(l0, l1) : pack2(h0, h1);
                    }
                    *(uint4*)((char*)sm + nb * bufstride + dstoff[s]) =
                        make_uint4(w[0], w[1], w[2], w[3]);
                }
            }
            asm volatile("cp.async.commit_group;");
        }

        // ---- fragments from buf ----
        unsigned aoff = buf * bufstride;
        unsigned boff = aoff;   // same stride layout; B regions at sel=1
        unsigned Ah[4][4], Al[4][4], Bh[2][4], Bl[2][4];
#pragma unroll
        for (int mf = 0; mf < 4; mf++) {
            unsigned r = (wm + mf * 16 + ldrow) * APITCH + ldk;
            ldsm4(Ah[mf], smb + aoff + (0 * 3072 + r) * 2);
            ldsm4(Al[mf], smb + aoff + (1 * 3072 + r) * 2);
        }
#pragma unroll
        for (int nh = 0; nh < 2; nh++) {
            unsigned r = (wn + nh * 16 + ldrow) * APITCH + ldk;
            ldsm4(Bh[nh], smb + boff + (4 * 3072 + r) * 2);
            ldsm4(Bl[nh], smb + boff + (5 * 3072 + r) * 2);
        }
#pragma unroll
        for (int mf = 0; mf < 4; mf++)
#pragma unroll
            for (int nf = 0; nf < 4; nf++) {
                int nh = nf >> 1, sel = nf & 1;
                unsigned bh0 = Bh[nh][sel], bh1 = Bh[nh][sel + 2];
                unsigned bl0 = Bl[nh][sel], bl1 = Bl[nh][sel + 2];
                mma_bf16(acc[mf][nf], Ah[mf], bh0, bh1);   // hi*hi
                mma_bf16(acc[mf][nf], Ah[mf], bl0, bl1);   // hi*lo
                mma_bf16(acc[mf][nf], Al[mf], bh0, bh1);   // lo*hi
            }
    }

    // ---- epilogue: fp32 acc -> fp16 AB ----
    int g = lane >> 2, tg = lane & 3;
    unsigned* outw = (unsigned*)g_abh2;
#pragma unroll
    for (int mf = 0; mf < 4; mf++)
#pragma unroll
        for (int nf = 0; nf < 4; nf++) {
            int col = n0 + wn + nf * 8 + 2 * tg;
            int r0 = m0 + wm + mf * 16 + g;
            if (r0 < Nn) {
                __half2 p = __floats2half2_rn(acc[mf][nf][0], acc[mf][nf][1]);
                outw[(size_t)r0 * 128 + (col >> 1)] = *(unsigned*)&p;
            }
            int r1 = r0 + 8;
            if (r1 < Nn) {
                __half2 p = __floats2half2_rn(acc[mf][nf][2], acc[mf][nf][3]);
                outw[(size_t)r1 * 128 + (col >> 1)] = *(unsigned*)&p;
            }
        }
}

// ---------------- edge stage: one warp per edge, fp16 gathers ----------------
__global__ __launch_bounds__(256) void k_edge(float* __restrict__ out,
                                              const float4* __restrict__ w2,
                                              const float* __restrict__ b2, int E) {
    int gt = blockIdx.x * 256 + threadIdx.x;
    int e = gt >> 5, lane = gt & 31;
    if (e >= E) return;
    int h = g_hh[e], t = g_tt[e], r = g_rr[e];
    uint2 ua = __ldg(&g_abh2[(size_t)h * 64 + lane]);        // cols 0..127
    uint2 ub = __ldg(&g_abh2[(size_t)t * 64 + 32 + lane]);   // cols 128..255
    uint2 ur = __ldg(&g_rh2[(size_t)r * 32 + lane]);         // R' (c folded in)
    float4 w  = __ldg(&w2[lane]);
    float2 a0 = __half22float2(*(__half2*)&ua.x), a1 = __half22float2(*(__half2*)&ua.y);
    float2 b0 = __half22float2(*(__half2*)&ub.x), b1 = __half22float2(*(__half2*)&ub.y);
    float2 r0 = __half22float2(*(__half2*)&ur.x), r1 = __half22float2(*(__half2*)&ur.y);
    float s = fmaxf(a0.x + b0.x + r0.x, 0.f) * w.x
            + fmaxf(a0.y + b0.y + r0.y, 0.f) * w.y
            + fmaxf(a1.x + b1.x + r1.x, 0.f) * w.z
            + fmaxf(a1.y + b1.y + r1.y, 0.f) * w.w;
    s += __shfl_xor_sync(0xffffffff, s, 16);
    s += __shfl_xor_sync(0xffffffff, s, 8);
    s += __shfl_xor_sync(0xffffffff, s, 4);
    s += __shfl_xor_sync(0xffffffff, s, 2);
    s += __shfl_xor_sync(0xffffffff, s, 1);
    if (lane == 0) out[e] = s + __ldg(b2);
}

// ---------------------------------------------------------------------------
extern "C" void kernel_launch(void* const* d_in, const int* in_sizes, int n_in,
                              void* d_out, int out_size) {
    int off = (n_in >= 13) ? 0 : -1;   // robust to scalar input being dropped
    const void*  ph    = d_in[0];
    const void*  pr    = d_in[1];
    const void*  pt    = d_in[2];
    const float* q     = (const float*)d_in[3];
    const float* ent   = (const float*)d_in[4];
    const float* rel   = (const float*)d_in[6 + off];
    const float* topic = (const float*)d_in[7 + off];
    const float* nont  = (const float*)d_in[8 + off];
    const float* W1    = (const float*)d_in[9 + off];
    const float* b1    = (const float*)d_in[10 + off];
    const float* W2    = (const float*)d_in[11 + off];
    const float* b2    = (const float*)d_in[12 + off];

    int E     = in_sizes[0];
    int Ntext = in_sizes[4] / 128;
    int NREL  = in_sizes[6 + off] / 128;
    int Nn    = in_sizes[7 + off] / 2;
    if (E > E_MAX) E = E_MAX;
    if (Nn > N_MAX) Nn = N_MAX;
    if (NREL > 512) NREL = 512;

    int gE = (E + 255) / 256;
    int nrelb = (NREL + 1) / 2;

    k_fill<<<(Nn * 32 + 255) / 256, 256>>>(ent, nont, Nn, Ntext);
    k_convert<<<gE, 256>>>(ph, pr, pt, topic, E);   // ids + counts + DDE round 0
    k_scat<<<gE, 256>>>(1, E);                      // DDE round 1 -> 2
    k_scat<<<gE, 256>>>(2, E);                      // DDE round 2 -> 3
    k_prep<<<144 + nrelb, 256>>>(W1, rel, q, b1, NREL);

    dim3 ggrid((Nn + 127) / 128, 2);
    k_gemm<<<ggrid, 256>>>(topic, Nn);

    k_edge<<<(E * 32 + 255) / 256, 256>>>((float*)d_out, (const float4*)W2, b2, E);
}

// round 5
// speedup vs baseline: 2.0958x; 1.3642x over previous
#include <cuda_runtime.h>
#include <cuda_bf16.h>
#include <cuda_fp16.h>

// ---------------------------------------------------------------------------
// Retriever: out[e] = relu([q | h_e[h] | r_emb[r] | h_e[t]] @ W1 + b1) @ W2 + b2
//   R'     = rel_embs @ W1[270:398] + (q @ W1[0:128] + b1)    (500 x 128, fp16)
//   AB     = h_e @ [W1[128:270] | W1[398:540]]                (N x 256, fp16)
//            split-bf16 tensor-core GEMM (3 HMMA products, fp32 accum),
//            inputs pre-split to bf16 hi/lo; DDE columns synthesized in-GEMM.
//   out[e] = W2 . relu(AB[h,0:128] + AB[t,128:256] + R'[r]) + b2
// DDE state: round0 accumulators carry the degree count in .z (one red.v4
// per direction per edge); later rounds use red.v2.
// ---------------------------------------------------------------------------

#define E_MAX 500000
#define N_MAX 100000
#define HE_W  144      // padded row width (142 used): pitch for he / Wcat (bf16)

__device__ int    g_hh[E_MAX];
__device__ int    g_tt[E_MAX];
__device__ int    g_rr[E_MAX];
__device__ float4 g_f0[N_MAX];                         // fwd r1 sums + cnt_t in .z
__device__ float4 g_r0[N_MAX];                         // rev r1 sums + cnt_h in .z
__device__ float2 g_f1[N_MAX], g_f2[N_MAX];            // fwd rounds 2,3 sums
__device__ float2 g_r1[N_MAX], g_r2[N_MAX];            // rev rounds 2,3 sums
__device__ __nv_bfloat16 g_heh[(size_t)N_MAX * HE_W];  // h_e hi (cols 0..127 filled)
__device__ __nv_bfloat16 g_hel[(size_t)N_MAX * HE_W];  // h_e lo
__device__ __nv_bfloat16 g_wh[256 * HE_W];             // Wcat hi, [n][k]
__device__ __nv_bfloat16 g_wl[256 * HE_W];             // Wcat lo
__device__ uint4  g_ab[(size_t)N_MAX * 32];            // AB  [N,256] fp16
__device__ uint4  g_rp[512 * 16];                      // R' [NREL,128] fp16

__device__ __forceinline__ unsigned pack2(__nv_bfloat16 x, __nv_bfloat16 y) {
    __nv_bfloat162 t = __halves2bfloat162(x, y);
    return *(unsigned*)&t;
}
__device__ __forceinline__ void split1(float v, __nv_bfloat16& h, __nv_bfloat16& l) {
    h = __float2bfloat16(v);
    l = __float2bfloat16(v - __bfloat162float(h));
}
__device__ __forceinline__ void red2(float2* p, float x, float y) {
    asm volatile("red.global.add.v2.f32 [%0], {%1, %2};"
                 :: "l"(p), "f"(x), "f"(y) : "memory");
}
__device__ __forceinline__ void red4(float4* p, float x, float y, float z, float w) {
    asm volatile("red.global.add.v4.f32 [%0], {%1, %2, %3, %4};"
                 :: "l"(p), "f"(x), "f"(y), "f"(z), "f"(w) : "memory");
}

// ---------------- build h_e hi/lo cols 0..127 + zero DDE state ----------------
__global__ void k_fill(const float* __restrict__ ent, const float* __restrict__ nont,
                       int Nn, int Ntext) {
    int i = blockIdx.x * 256 + threadIdx.x;
    if (i >= Nn * 32) return;
    int node = i >> 5, c4 = i & 31;
    const float* src = (node < Ntext) ? (ent + (size_t)node * 128 + c4 * 4)
                                      : (nont + c4 * 4);
    float4 v = *(const float4*)src;
    __nv_bfloat16 hx, hy, hz, hw, lx, ly, lz, lw;
    split1(v.x, hx, lx); split1(v.y, hy, ly);
    split1(v.z, hz, lz); split1(v.w, hw, lw);
    size_t off = (size_t)node * HE_W + c4 * 4;
    *(uint2*)(g_heh + off) = make_uint2(pack2(hx, hy), pack2(hz, hw));
    *(uint2*)(g_hel + off) = make_uint2(pack2(lx, ly), pack2(lz, lw));
    if (c4 == 0) {   // piggyback: zero DDE accumulators
        g_f0[node] = make_float4(0.f, 0.f, 0.f, 0.f);
        g_r0[node] = make_float4(0.f, 0.f, 0.f, 0.f);
        g_f1[node] = make_float2(0.f, 0.f);
        g_f2[node] = make_float2(0.f, 0.f);
        g_r1[node] = make_float2(0.f, 0.f);
        g_r2[node] = make_float2(0.f, 0.f);
    }
}

// ------- ids -> int32 (+dtype detect) + DDE round 0 (sums + counts, red.v4) ---
__global__ void k_convert(const void* ph, const void* pr, const void* pt,
                          const float* __restrict__ topic, int E) {
    __shared__ int s64;
    if (threadIdx.x == 0) {
        // int64 vs int32: int64 view of int32 r-id buffer is >= 2^32 a.s.
        const long long* p = (const long long*)ph;
        const long long* qq = (const long long*)pr;
        int ok = 1;
        for (int i = 0; i < 8; i++) {
            long long v = p[i];  if (v < 0 || v >= 1000000) ok = 0;
            long long w = qq[i]; if (w < 0 || w >= 1000000) ok = 0;
        }
        s64 = ok;
    }
    __syncthreads();
    int e = blockIdx.x * 256 + threadIdx.x;
    if (e >= E) return;
    int h, r, t;
    if (s64) {
        h = (int)((const long long*)ph)[e];
        r = (int)((const long long*)pr)[e];
        t = (int)((const long long*)pt)[e];
    } else {
        h = ((const int*)ph)[e];
        r = ((const int*)pr)[e];
        t = ((const int*)pt)[e];
    }
    g_hh[e] = h; g_rr[e] = r; g_tt[e] = t;
    const float2* tp2 = (const float2*)topic;
    float2 th = __ldg(tp2 + h);
    float2 tt = __ldg(tp2 + t);
    red4(&g_f0[t], th.x, th.y, 1.0f, 0.f);   // fwd: h -> t  (+count)
    red4(&g_r0[h], tt.x, tt.y, 1.0f, 0.f);   // rev: t -> h  (+count)
}

// ------- DDE scatter round rd (1 or 2): normalize prev sums, red.v2 ------------
__global__ void k_scat(int rd, int E) {
    int e = blockIdx.x * 256 + threadIdx.x;
    if (e >= E) return;
    int h = g_hh[e], t = g_tt[e];
    if (rd == 1) {
        float4 f0h = __ldg(&g_f0[h]);
        float4 r0t = __ldg(&g_r0[t]);
        float ict = 1.0f / fmaxf(f0h.z, 1.0f);
        float ich = 1.0f / fmaxf(r0t.z, 1.0f);
        red2(&g_f1[t], f0h.x * ict, f0h.y * ict);
        red2(&g_r1[h], r0t.x * ich, r0t.y * ich);
    } else {
        float cth = __ldg(((const float*)g_f0) + 4 * (size_t)h + 2);
        float cht = __ldg(((const float*)g_r0) + 4 * (size_t)t + 2);
        float2 f1h = __ldg(&g_f1[h]);
        float2 r1t = __ldg(&g_r1[t]);
        float ict = 1.0f / fmaxf(cth, 1.0f);
        float ich = 1.0f / fmaxf(cht, 1.0f);
        red2(&g_f2[t], f1h.x * ict, f1h.y * ict);
        red2(&g_r2[h], r1t.x * ich, r1t.y * ich);
    }
}

// ------- prep: Wcat split-bf16 [n][k] | R' = rel@W1_r + (q@W1_q + b1), fp16 ----
__global__ void k_prep(const float* __restrict__ W1, const float* __restrict__ rel,
                       const float* __restrict__ q, const float* __restrict__ b1,
                       int NREL) {
    int bid = blockIdx.x;
    int tid = threadIdx.x;
    if (bid < 144) {                       // Wcat: 256 elements of the [n][k] array
        int idx = bid * 256 + tid;
        int n = idx / 144, k = idx % 144;
        float v = 0.f;
        if (k < 142) v = (n < 128) ? W1[(128 + k) * 128 + n]
                                   : W1[(398 + k) * 128 + (n - 128)];
        __nv_bfloat16 h, l;
        split1(v, h, l);
        g_wh[idx] = h;
        g_wl[idx] = l;
    } else {                               // two relations per block
        __shared__ float rs[256];
        __shared__ float qs[128];
        int r = (bid - 144) * 2 + (tid >> 7);
        int j = tid & 127;
        int base = tid & ~127;
        if (tid < 128) qs[tid] = q[tid];
        rs[tid] = (r < NREL) ? rel[(size_t)r * 128 + j] : 0.f;
        __syncthreads();
        if (r < NREL) {
            float accc = b1[j];
#pragma unroll 8
            for (int k = 0; k < 128; k++) accc += qs[k] * __ldg(&W1[k * 128 + j]);
            float accr = 0.f;
#pragma unroll 8
            for (int k = 0; k < 128; k++) accr += rs[base + k] * __ldg(&W1[(270 + k) * 128 + j]);
            ((__half*)g_rp)[(size_t)r * 128 + j] = __float2half(accc + accr);
        }
    }
}

// ---------------------------------------------------------------------------
// GEMM: AB[N,256] = h_e[N,144] @ Wcat[144,256], split-bf16 (3 products).
// Block 128(m) x 128(n), 8 warps (2x4), warp tile 64x32, BK=16.
// cp.async double-buffered staging; last k-tile (cols 128..143) synthesized
// from topic + DDE accumulators.
// ---------------------------------------------------------------------------
#define APITCH 24   // smem row pitch in bf16 (48B -> conflict-free ldmatrix)

__device__ __forceinline__ void ldsm4(unsigned* r, unsigned a) {
    asm volatile("ldmatrix.sync.aligned.m8n8.x4.shared.b16 {%0,%1,%2,%3}, [%4];"
                 : "=r"(r[0]), "=r"(r[1]), "=r"(r[2]), "=r"(r[3]) : "r"(a));
}
__device__ __forceinline__ void mma_bf16(float* d, const unsigned* a, unsigned b0, unsigned b1) {
    asm volatile("mma.sync.aligned.m16n8k16.row.col.f32.bf16.bf16.f32 "
                 "{%0,%1,%2,%3}, {%4,%5,%6,%7}, {%8,%9}, {%0,%1,%2,%3};"
                 : "+f"(d[0]), "+f"(d[1]), "+f"(d[2]), "+f"(d[3])
                 : "r"(a[0]), "r"(a[1]), "r"(a[2]), "r"(a[3]), "r"(b0), "r"(b1));
}
__device__ __forceinline__ void cp16(unsigned dst, const void* src) {
    asm volatile("cp.async.ca.shared.global [%0], [%1], 16;" :: "r"(dst), "l"(src));
}

__global__ __launch_bounds__(256) void k_gemm(const float* __restrict__ topic, int Nn) {
    // smem: [sel(A/B)][buf][arr(hi/lo)][128*APITCH] bf16 = 48 KB
    __shared__ __align__(16) __nv_bfloat16 sm[8 * 128 * APITCH];
    unsigned smb = (unsigned)__cvta_generic_to_shared(sm);
    int tid = threadIdx.x;
    int m0 = blockIdx.x * 128, n0 = blockIdx.y * 128;
    int wid = tid >> 5, lane = tid & 31;
    int wm = (wid >> 2) * 64, wn = (wid & 3) * 32;

    // staging map: 4 slots/thread. slots 0,1 -> A ; 2,3 -> B.
    int srow[4], shalf[4], sarr[4];
    const __nv_bfloat16* gbase[4];
    unsigned dstoff[4];   // smem byte offset excluding buf
#pragma unroll
    for (int s = 0; s < 4; s++) {
        int idx = tid + 256 * s;
        int sel = idx >> 9;            // 0 = A, 1 = B
        int rem = idx & 511;
        int row = rem >> 2, qq = rem & 3;
        int arr = qq >> 1, half = qq & 1;
        srow[s] = row; shalf[s] = half; sarr[s] = arr;
        if (sel == 0) {
            int gr = m0 + row; if (gr >= Nn) gr = Nn - 1;
            gbase[s] = (arr ? g_hel : g_heh) + (size_t)gr * HE_W + half * 8;
        } else {
            gbase[s] = (arr ? g_wl : g_wh) + (size_t)(n0 + row) * HE_W + half * 8;
        }
        dstoff[s] = ((unsigned)(sel * 4 + arr) * 3072 + row * APITCH + half * 8) * 2;
    }
    const unsigned bufstride = 2u * 3072u * 2u;   // bytes between buf0/buf1 regions

    float acc[4][4][4];
#pragma unroll
    for (int i = 0; i < 4; i++)
#pragma unroll
        for (int j = 0; j < 4; j++)
#pragma unroll
            for (int k = 0; k < 4; k++) acc[i][j][k] = 0.f;

    int ldrow = lane & 15, ldk = (lane >> 4) * 8;

    // ---- prologue: stage tile 0 into buf 0 ----
#pragma unroll
    for (int s = 0; s < 4; s++) cp16(smb + dstoff[s], gbase[s]);
    asm volatile("cp.async.commit_group;");

    for (int it = 0; it <= 8; ++it) {
        int buf = it & 1;
        asm volatile("cp.async.wait_group 0;");
        __syncthreads();

        if (it < 8) {
            int nb = buf ^ 1;
            unsigned bofs = nb * bufstride;
            if (it + 1 < 8) {
#pragma unroll
                for (int s = 0; s < 4; s++)
                    cp16(smb + bofs + dstoff[s], gbase[s] + (it + 1) * 16);
            } else {
                // tile 8: B via cp.async; A synthesized from topic + DDE state.
#pragma unroll
                for (int s = 2; s < 4; s++)
                    cp16(smb + bofs + dstoff[s], gbase[s] + 8 * 16);
#pragma unroll
                for (int s = 0; s < 2; s++) {
                    int row = srow[s], half = shalf[s], arr = sarr[s];
                    int i = m0 + row; if (i >= Nn) i = Nn - 1;
                    float v[8];
                    if (half == 0) {  // cols 128..135: topic, fwd rounds 1..3
                        float2 tp = __ldg(((const float2*)topic) + i);
                        float4 f0 = g_f0[i];
                        float2 f1 = g_f1[i], f2 = g_f2[i];
                        float ict = 1.0f / fmaxf(f0.z, 1.0f);
                        v[0] = tp.x;       v[1] = tp.y;
                        v[2] = f0.x * ict; v[3] = f0.y * ict;
                        v[4] = f1.x * ict; v[5] = f1.y * ict;
                        v[6] = f2.x * ict; v[7] = f2.y * ict;
                    } else {          // cols 136..143: rev rounds 1..3, pad
                        float4 r0 = g_r0[i];
                        float2 r1 = g_r1[i], r2 = g_r2[i];
                        float ich = 1.0f / fmaxf(r0.z, 1.0f);
                        v[0] = r0.x * ich; v[1] = r0.y * ich;
                        v[2] = r1.x * ich; v[3] = r1.y * ich;
                        v[4] = r2.x * ich; v[5] = r2.y * ich;
                        v[6] = 0.f;        v[7] = 0.f;
                    }
                    unsigned w[4];
#pragma unroll
                    for (int p = 0; p < 4; p++) {
                        __nv_bfloat16 h0, l0, h1, l1;
                        split1(v[2 * p], h0, l0);
                        split1(v[2 * p + 1], h1, l1);
                        w[p] = arr ? pack2(l0, l1) : pack2(h0, h1);
                    }
                    *(uint4*)((char*)sm + nb * bufstride + dstoff[s]) =
                        make_uint4(w[0], w[1], w[2], w[3]);
                }
            }
            asm volatile("cp.async.commit_group;");
        }

        // ---- fragments from buf ----
        unsigned aoff = buf * bufstride;
        unsigned Ah[4][4], Al[4][4], Bh[2][4], Bl[2][4];
#pragma unroll
        for (int mf = 0; mf < 4; mf++) {
            unsigned r = (wm + mf * 16 + ldrow) * APITCH + ldk;
            ldsm4(Ah[mf], smb + aoff + (0 * 3072 + r) * 2);
            ldsm4(Al[mf], smb + aoff + (1 * 3072 + r) * 2);
        }
#pragma unroll
        for (int nh = 0; nh < 2; nh++) {
            unsigned r = (wn + nh * 16 + ldrow) * APITCH + ldk;
            ldsm4(Bh[nh], smb + aoff + (4 * 3072 + r) * 2);
            ldsm4(Bl[nh], smb + aoff + (5 * 3072 + r) * 2);
        }
#pragma unroll
        for (int mf = 0; mf < 4; mf++)
#pragma unroll
            for (int nf = 0; nf < 4; nf++) {
                int nh = nf >> 1, sel = nf & 1;
                unsigned bh0 = Bh[nh][sel], bh1 = Bh[nh][sel + 2];
                unsigned bl0 = Bl[nh][sel], bl1 = Bl[nh][sel + 2];
                mma_bf16(acc[mf][nf], Ah[mf], bh0, bh1);   // hi*hi
                mma_bf16(acc[mf][nf], Ah[mf], bl0, bl1);   // hi*lo
                mma_bf16(acc[mf][nf], Al[mf], bh0, bh1);   // lo*hi
            }
    }

    // ---- epilogue: fp32 acc -> fp16 AB ----
    int g = lane >> 2, tg = lane & 3;
    unsigned* outw = (unsigned*)g_ab;
#pragma unroll
    for (int mf = 0; mf < 4; mf++)
#pragma unroll
        for (int nf = 0; nf < 4; nf++) {
            int col = n0 + wn + nf * 8 + 2 * tg;
            int r0 = m0 + wm + mf * 16 + g;
            if (r0 < Nn) {
                __half2 p = __floats2half2_rn(acc[mf][nf][0], acc[mf][nf][1]);
                outw[(size_t)r0 * 128 + (col >> 1)] = *(unsigned*)&p;
            }
            int r1 = r0 + 8;
            if (r1 < Nn) {
                __half2 p = __floats2half2_rn(acc[mf][nf][2], acc[mf][nf][3]);
                outw[(size_t)r1 * 128 + (col >> 1)] = *(unsigned*)&p;
            }
        }
}

// -------- edge stage: 16 lanes per edge, uint4 (LDG.128) gathers --------------
__device__ __forceinline__ float2 h22f(unsigned u) {
    return __half22float2(*(__half2*)&u);
}
__global__ __launch_bounds__(256) void k_edge(float* __restrict__ out,
                                              const float4* __restrict__ w2,
                                              const float* __restrict__ b2, int E) {
    int gt = blockIdx.x * 256 + threadIdx.x;
    int e = gt >> 4, sub = gt & 15;
    bool valid = (e < E);
    if (e >= E) e = E - 1;
    int h = g_hh[e], t = g_tt[e], r = g_rr[e];
    uint4 ua = __ldg(&g_ab[(size_t)h * 32 + sub]);        // cols 8s..8s+7 of A
    uint4 ub = __ldg(&g_ab[(size_t)t * 32 + 16 + sub]);   // cols 8s..8s+7 of B
    uint4 ur = __ldg(&g_rp[(size_t)r * 16 + sub]);        // R' (c, b1 folded in)
    float4 w0 = __ldg(&w2[2 * sub]);
    float4 w1 = __ldg(&w2[2 * sub + 1]);
    float2 a0 = h22f(ua.x), a1 = h22f(ua.y), a2 = h22f(ua.z), a3 = h22f(ua.w);
    float2 b0 = h22f(ub.x), b1 = h22f(ub.y), b2v = h22f(ub.z), b3 = h22f(ub.w);
    float2 r0 = h22f(ur.x), r1 = h22f(ur.y), r2 = h22f(ur.z), r3 = h22f(ur.w);
    float s = fmaxf(a0.x + b0.x + r0.x, 0.f) * w0.x
            + fmaxf(a0.y + b0.y + r0.y, 0.f) * w0.y
            + fmaxf(a1.x + b1.x + r1.x, 0.f) * w0.z
            + fmaxf(a1.y + b1.y + r1.y, 0.f) * w0.w
            + fmaxf(a2.x + b2v.x + r2.x, 0.f) * w1.x
            + fmaxf(a2.y + b2v.y + r2.y, 0.f) * w1.y
            + fmaxf(a3.x + b3.x + r3.x, 0.f) * w1.z
            + fmaxf(a3.y + b3.y + r3.y, 0.f) * w1.w;
    s += __shfl_xor_sync(0xffffffff, s, 8);
    s += __shfl_xor_sync(0xffffffff, s, 4);
    s += __shfl_xor_sync(0xffffffff, s, 2);
    s += __shfl_xor_sync(0xffffffff, s, 1);
    if (valid && sub == 0) out[e] = s + __ldg(b2);
}

// ---------------------------------------------------------------------------
// Streams/events for fork-join overlap. Created in a static initializer (at
// process load, before the harness's device-memory checkpoints and before any
// graph capture), so kernel_launch itself performs no resource creation.
struct HxRes {
    cudaStream_t s1, s2;
    cudaEvent_t e0, e1, e2;
    HxRes() {
        cudaStreamCreateWithFlags(&s1, cudaStreamNonBlocking);
        cudaStreamCreateWithFlags(&s2, cudaStreamNonBlocking);
        cudaEventCreateWithFlags(&e0, cudaEventDisableTiming);
        cudaEventCreateWithFlags(&e1, cudaEventDisableTiming);
        cudaEventCreateWithFlags(&e2, cudaEventDisableTiming);
    }
};
static HxRes hx;

extern "C" void kernel_launch(void* const* d_in, const int* in_sizes, int n_in,
                              void* d_out, int out_size) {
    int off = (n_in >= 13) ? 0 : -1;   // robust to scalar input being dropped
    const void*  ph    = d_in[0];
    const void*  pr    = d_in[1];
    const void*  pt    = d_in[2];
    const float* q     = (const float*)d_in[3];
    const float* ent   = (const float*)d_in[4];
    const float* rel   = (const float*)d_in[6 + off];
    const float* topic = (const float*)d_in[7 + off];
    const float* nont  = (const float*)d_in[8 + off];
    const float* W1    = (const float*)d_in[9 + off];
    const float* b1    = (const float*)d_in[10 + off];
    const float* W2    = (const float*)d_in[11 + off];
    const float* b2    = (const float*)d_in[12 + off];

    int E     = in_sizes[0];
    int Ntext = in_sizes[4] / 128;
    int NREL  = in_sizes[6 + off] / 128;
    int Nn    = in_sizes[7 + off] / 2;
    if (E > E_MAX) E = E_MAX;
    if (Nn > N_MAX) Nn = N_MAX;
    if (NREL > 512) NREL = 512;

    int gE = (E + 255) / 256;
    int nrelb = (NREL + 1) / 2;

    // fork: fill on s1, prep on s2, DDE chain on the main stream
    cudaEventRecord(hx.e0, 0);
    cudaStreamWaitEvent(hx.s1, hx.e0, 0);
    cudaStreamWaitEvent(hx.s2, hx.e0, 0);

    k_fill<<<(Nn * 32 + 255) / 256, 256, 0, hx.s1>>>(ent, nont, Nn, Ntext);
    cudaEventRecord(hx.e1, hx.s1);

    k_prep<<<144 + nrelb, 256, 0, hx.s2>>>(W1, rel, q, b1, NREL);
    cudaEventRecord(hx.e2, hx.s2);

    k_convert<<<gE, 256>>>(ph, pr, pt, topic, E);   // ids + DDE round 0 + counts
    k_scat<<<gE, 256>>>(1, E);                      // DDE round 1 -> 2
    k_scat<<<gE, 256>>>(2, E);                      // DDE round 2 -> 3

    // join: gemm needs fill (+DDE, already on this stream)
    cudaStreamWaitEvent(0, hx.e1, 0);
    dim3 ggrid((Nn + 127) / 128, 2);
    k_gemm<<<ggrid, 256>>>(topic, Nn);

    // edge needs prep (R') and gemm
    cudaStreamWaitEvent(0, hx.e2, 0);
    k_edge<<<(E * 16 + 255) / 256, 256>>>((float*)d_out, (const float4*)W2, b2, E);
}